// round 13
// baseline (speedup 1.0000x reference)
#include <cuda_runtime.h>
#include <cuda_bf16.h>
#include <cstdint>

// MultiHeadAttention: B=2, N=2048, C=1024, H=16, D=64, fp32.
// R11 (resubmit after infra failure): ldmatrix.x4 fragment loads everywhere
// (GEMMs + attention S/PV). Otherwise identical math to R10 (bf16 hi/lo x3).

#define BB 2
#define NN 2048
#define CC 1024
#define HH 16
#define DD 64
#define MM (BB * NN)
#define SCALE_F 0.125f
#define CW (CC / 2)

#define NCH 32
#define SST 20
#define STW (128 * SST)
#define STW4 (STW * 4)
#define SMEM_GEMM (2 * 4 * STW4)   // 81920
#define SMEM_ATTN 65536

__device__ uint32_t g_xh[(size_t)MM * CW],  g_xl[(size_t)MM * CW];
__device__ uint32_t g_wqh[(size_t)3 * CC * CW], g_wql[(size_t)3 * CC * CW];
__device__ uint32_t g_wph[(size_t)CC * CW], g_wpl[(size_t)CC * CW];
__device__ uint32_t g_qh[(size_t)BB * HH * NN * DD / 2], g_ql[(size_t)BB * HH * NN * DD / 2];
__device__ uint32_t g_kh[(size_t)BB * HH * NN * DD / 2], g_kl[(size_t)BB * HH * NN * DD / 2];
__device__ uint32_t g_vh[(size_t)BB * HH * DD * NN / 2], g_vl[(size_t)BB * HH * DD * NN / 2];
__device__ uint32_t g_atth[(size_t)MM * CW], g_attl[(size_t)MM * CW];

extern __shared__ unsigned char dynsm[];

// ---------------------------------------------------------------------------
static __device__ __forceinline__ void mma16816(float* d, const uint32_t a[4],
                                                const uint32_t b[2]) {
    asm volatile(
        "mma.sync.aligned.m16n8k16.row.col.f32.bf16.bf16.f32 "
        "{%0,%1,%2,%3}, {%4,%5,%6,%7}, {%8,%9}, {%0,%1,%2,%3};"
        : "+f"(d[0]), "+f"(d[1]), "+f"(d[2]), "+f"(d[3])
        : "r"(a[0]), "r"(a[1]), "r"(a[2]), "r"(a[3]), "r"(b[0]), "r"(b[1]));
}
static __device__ __forceinline__ void ldmx4(uint32_t* r, uint32_t saddr) {
    asm volatile("ldmatrix.sync.aligned.m8n8.x4.shared.b16 {%0,%1,%2,%3}, [%4];"
                 : "=r"(r[0]), "=r"(r[1]), "=r"(r[2]), "=r"(r[3]) : "r"(saddr));
}
static __device__ __forceinline__ uint32_t packbf(float x0, float x1) {
    __nv_bfloat162 p = __halves2bfloat162(__float2bfloat16(x0), __float2bfloat16(x1));
    return *(uint32_t*)&p;
}
static __device__ __forceinline__ void cpa16(uint32_t dst, const uint32_t* src) {
    asm volatile("cp.async.ca.shared.global [%0], [%1], 16;"
                 :: "r"(dst), "l"(src) : "memory");
}
#define CP_COMMIT() asm volatile("cp.async.commit_group;" ::: "memory")
#define CP_WAIT(n)  asm volatile("cp.async.wait_group %0;" :: "n"(n) : "memory")

// ---------------------------------------------------------------------------
__global__ __launch_bounds__(256) void cvt_hilo(const float* __restrict__ src,
                                                uint32_t* __restrict__ hi,
                                                uint32_t* __restrict__ lo, int n4) {
    int i = blockIdx.x * blockDim.x + threadIdx.x;
    if (i >= n4) return;
    float4 v = ((const float4*)src)[i];
    __nv_bfloat16 h0 = __float2bfloat16(v.x), h1 = __float2bfloat16(v.y);
    __nv_bfloat16 h2 = __float2bfloat16(v.z), h3 = __float2bfloat16(v.w);
    uint32_t hw0 = packbf(v.x, v.y), hw1 = packbf(v.z, v.w);
    uint32_t lw0 = packbf(v.x - __bfloat162float(h0), v.y - __bfloat162float(h1));
    uint32_t lw1 = packbf(v.z - __bfloat162float(h2), v.w - __bfloat162float(h3));
    ((uint2*)hi)[i] = make_uint2(hw0, hw1);
    ((uint2*)lo)[i] = make_uint2(lw0, lw1);
}

// ---------------------------------------------------------------------------
// GEMM: acc = A[row0:+128,:] @ B[col0:+128,:]^T, ldmatrix fragment loads.
// ---------------------------------------------------------------------------
static __device__ __forceinline__ void prefetch4(const uint32_t* __restrict__ Ah,
                                                 const uint32_t* __restrict__ Al,
                                                 const uint32_t* __restrict__ Bh,
                                                 const uint32_t* __restrict__ Bl,
                                                 int row0, int col0, int c,
                                                 uint32_t sbase, int t) {
#pragma unroll
    for (int i = 0; i < 2; i++) {
        int idx = t + i * 256;
        int row = idx >> 2, q = (idx & 3) * 4;
        uint32_t doff = (uint32_t)(row * SST + q) * 4u;
        size_t aoff = (size_t)(row0 + row) * CW + c * 16 + q;
        size_t boff = (size_t)(col0 + row) * CW + c * 16 + q;
        cpa16(sbase + doff,            Ah + aoff);
        cpa16(sbase + STW4 + doff,     Al + aoff);
        cpa16(sbase + 2 * STW4 + doff, Bh + boff);
        cpa16(sbase + 3 * STW4 + doff, Bl + boff);
    }
}

static __device__ __forceinline__ void bf16gemm(const uint32_t* __restrict__ Ah,
                                                const uint32_t* __restrict__ Al,
                                                const uint32_t* __restrict__ Bh,
                                                const uint32_t* __restrict__ Bl,
                                                int row0, int col0, float acc[2][8][4]) {
    const int t = threadIdx.x;
    const int wid = t >> 5, lane = t & 31;
    const int wm = wid & 3, wn = wid >> 2;
    const int lrow = lane & 7, grp = lane >> 3;
    const uint32_t sb = (uint32_t)__cvta_generic_to_shared(dynsm);

    const int rpart = lrow + ((grp & 1) << 3);
    const int cadd = (grp >> 1) << 2;          // +0 or +4 u32

    prefetch4(Ah, Al, Bh, Bl, row0, col0, 0, sb, t);
    CP_COMMIT();

    for (int c = 0; c < NCH; c++) {
        const int buf = c & 1;
        if (c + 1 < NCH) {
            prefetch4(Ah, Al, Bh, Bl, row0, col0, c + 1,
                      sb + (uint32_t)((c + 1) & 1) * 4 * STW4, t);
            CP_COMMIT();
            CP_WAIT(1);
        } else {
            CP_WAIT(0);
        }
        __syncthreads();

        const uint32_t base = sb + (uint32_t)buf * 4 * STW4;
#pragma unroll
        for (int k16 = 0; k16 < 2; k16++) {
            const int colu = k16 * 8 + cadd;
            uint32_t afh[2][4], afl[2][4];
#pragma unroll
            for (int mf = 0; mf < 2; mf++) {
                const int r = wm * 32 + mf * 16 + rpart;
                const uint32_t off = (uint32_t)(r * SST + colu) * 4u;
                ldmx4(afh[mf], base + off);
                ldmx4(afl[mf], base + STW4 + off);
            }
#pragma unroll
            for (int nfp = 0; nfp < 4; nfp++) {
                const int n = wn * 64 + nfp * 16 + rpart;
                const uint32_t off = (uint32_t)(n * SST + colu) * 4u;
                uint32_t bfh[4], bfl[4];
                ldmx4(bfh, base + 2 * STW4 + off);
                ldmx4(bfl, base + 3 * STW4 + off);
                uint32_t b0h[2] = {bfh[0], bfh[2]}, b1h[2] = {bfh[1], bfh[3]};
                uint32_t b0l[2] = {bfl[0], bfl[2]}, b1l[2] = {bfl[1], bfl[3]};
#pragma unroll
                for (int mf = 0; mf < 2; mf++) {
                    mma16816(acc[mf][2 * nfp],     afh[mf], b0h);
                    mma16816(acc[mf][2 * nfp],     afl[mf], b0h);
                    mma16816(acc[mf][2 * nfp],     afh[mf], b0l);
                    mma16816(acc[mf][2 * nfp + 1], afh[mf], b1h);
                    mma16816(acc[mf][2 * nfp + 1], afl[mf], b1h);
                    mma16816(acc[mf][2 * nfp + 1], afh[mf], b1l);
                }
            }
        }
        __syncthreads();
    }
}

// ---------------------------------------------------------------------------
// qkv: x @ w_qkv^T -> Q,K [B,H,N,D] hi/lo (Q pre-scaled), V [B,H,D,N] hi/lo
// ---------------------------------------------------------------------------
__global__ __launch_bounds__(256, 2) void qkv_mma() {
    const int row0 = blockIdx.y * 128;
    const int col0 = blockIdx.x * 128;
    float acc[2][8][4] = {};
    bf16gemm(g_xh, g_xl, g_wqh, g_wql, row0, col0, acc);

    const int t = threadIdx.x, wid = t >> 5, lane = t & 31;
    const int wm = wid & 3, wn = wid >> 2;
    const int lr = lane >> 2, lc2 = lane & 3;
    const int which = col0 >> 10;
    const int colrem0 = (col0 & (CC - 1)) + wn * 64;
#pragma unroll
    for (int mf = 0; mf < 2; mf++) {
        const int rbase = row0 + wm * 32 + mf * 16 + lr;
#pragma unroll
        for (int half = 0; half < 2; half++) {
            const int r = rbase + half * 8;
            const int b = r >> 11, n = r & (NN - 1);
#pragma unroll
            for (int nf = 0; nf < 8; nf++) {
                const int c = colrem0 + nf * 8 + lc2 * 2;
                float v0 = acc[mf][nf][half * 2];
                float v1 = acc[mf][nf][half * 2 + 1];
                const int h = c >> 6, d = c & 63;
                if (which == 0) { v0 *= SCALE_F; v1 *= SCALE_F; }
                __nv_bfloat16 h0 = __float2bfloat16(v0);
                __nv_bfloat16 h1 = __float2bfloat16(v1);
                __nv_bfloat16 e0 = __float2bfloat16(v0 - __bfloat162float(h0));
                __nv_bfloat16 e1 = __float2bfloat16(v1 - __bfloat162float(h1));
                if (which == 2) {
                    size_t base = ((size_t)(b * HH + h) * DD + d) * NN + n;
                    __nv_bfloat16* vh = (__nv_bfloat16*)g_vh;
                    __nv_bfloat16* vl = (__nv_bfloat16*)g_vl;
                    vh[base] = h0; vh[base + NN] = h1;
                    vl[base] = e0; vl[base + NN] = e1;
                } else {
                    __nv_bfloat162 hp = __halves2bfloat162(h0, h1);
                    __nv_bfloat162 lp = __halves2bfloat162(e0, e1);
                    uint32_t* ah = which ? g_kh : g_qh;
                    uint32_t* al = which ? g_kl : g_ql;
                    size_t idx = ((size_t)(b * HH + h) * NN + n) * 32 + (d >> 1);
                    ah[idx] = *(uint32_t*)&hp;
                    al[idx] = *(uint32_t*)&lp;
                }
            }
        }
    }
}

// ---------------------------------------------------------------------------
// Attention: R10 math, ldmatrix fragment loads for K and V.
// ---------------------------------------------------------------------------
__global__ __launch_bounds__(256) void attn_mma() {
    uint32_t* Ksh = (uint32_t*)dynsm;
    uint32_t* Ksl = Ksh + 4096;
    uint32_t* Vsh = Ksl + 4096;
    uint32_t* Vsl = Vsh + 4096;
    const int t = threadIdx.x, wid = t >> 5, lane = t & 31;
    const int lr = lane >> 2, lc2 = lane & 3;
    const int lrow = lane & 7, grp = lane >> 3;
    const int rpart = lrow + ((grp & 1) << 3);
    const int cadd2 = (grp >> 1);              // 0/1: which 16B half
    const int bh = blockIdx.z * HH + blockIdx.y;
    const int q0 = blockIdx.x * 128;
    const uint32_t sb = (uint32_t)__cvta_generic_to_shared(dynsm);
    const uint32_t sKh = sb, sKl = sb + 16384, sVh = sb + 32768, sVl = sb + 49152;

    uint32_t qh[4][4], ql[4][4];
    {
        const size_t rbase = ((size_t)bh * NN + q0 + wid * 16) * 32;
        const uint32_t* r0h = g_qh + rbase + (size_t)lr * 32;
        const uint32_t* r1h = r0h + 8 * 32;
        const uint32_t* r0l = g_ql + rbase + (size_t)lr * 32;
        const uint32_t* r1l = r0l + 8 * 32;
#pragma unroll
        for (int c = 0; c < 4; c++) {
            qh[c][0] = r0h[8 * c + lc2];     qh[c][1] = r1h[8 * c + lc2];
            qh[c][2] = r0h[8 * c + lc2 + 4]; qh[c][3] = r1h[8 * c + lc2 + 4];
            ql[c][0] = r0l[8 * c + lc2];     ql[c][1] = r1l[8 * c + lc2];
            ql[c][2] = r0l[8 * c + lc2 + 4]; ql[c][3] = r1l[8 * c + lc2 + 4];
        }
    }

    float o[8][4] = {};
    float m0 = -1e30f, m1 = -1e30f, l0 = 0.f, l1 = 0.f;

    const uint4* gkh = (const uint4*)g_kh + ((size_t)bh * NN) * 8;
    const uint4* gkl = (const uint4*)g_kl + ((size_t)bh * NN) * 8;
    const uint4* gvh = (const uint4*)g_vh + ((size_t)bh * DD) * 256;
    const uint4* gvl = (const uint4*)g_vl + ((size_t)bh * DD) * 256;

    for (int k0 = 0; k0 < NN; k0 += 128) {
        __syncthreads();
#pragma unroll
        for (int i = 0; i < 4; i++) {
            int idx = t + i * 256;
            int key = idx >> 3, c4 = idx & 7;
            int dst = key * 8 + (c4 ^ (key & 7));
            ((uint4*)Ksh)[dst] = gkh[(size_t)(k0 + key) * 8 + c4];
            ((uint4*)Ksl)[dst] = gkl[(size_t)(k0 + key) * 8 + c4];
            int d = idx >> 4, v4 = idx & 15;
            int vdst = d * 16 + (v4 ^ (d & 7));
            ((uint4*)Vsh)[vdst] = gvh[(size_t)d * 256 + (k0 >> 3) + v4];
            ((uint4*)Vsl)[vdst] = gvl[(size_t)d * 256 + (k0 >> 3) + v4];
        }
        __syncthreads();

        // S = Q K^T, ldmatrix K fragments (2 t16 tiles per x4)
        float s[16][4] = {};
#pragma unroll
        for (int c = 0; c < 4; c++) {
#pragma unroll
            for (int tp = 0; tp < 8; tp++) {
                const int key = 16 * tp + rpart;
                const uint32_t off =
                    (uint32_t)(key * 32 + (((2 * c + cadd2) ^ (key & 7)) << 2)) * 4u;
                uint32_t kh4[4], kl4[4];
                ldmx4(kh4, sKh + off);
                ldmx4(kl4, sKl + off);
                uint32_t b0h[2] = {kh4[0], kh4[2]}, b1h[2] = {kh4[1], kh4[3]};
                uint32_t b0l[2] = {kl4[0], kl4[2]}, b1l[2] = {kl4[1], kl4[3]};
                mma16816(s[2 * tp], qh[c], b0h);
                mma16816(s[2 * tp], ql[c], b0h);
                mma16816(s[2 * tp], qh[c], b0l);
                mma16816(s[2 * tp + 1], qh[c], b1h);
                mma16816(s[2 * tp + 1], ql[c], b1h);
                mma16816(s[2 * tp + 1], qh[c], b1l);
            }
        }

        // online softmax
        float mx0 = -1e30f, mx1 = -1e30f;
#pragma unroll
        for (int t16 = 0; t16 < 16; t16++) {
            mx0 = fmaxf(mx0, fmaxf(s[t16][0], s[t16][1]));
            mx1 = fmaxf(mx1, fmaxf(s[t16][2], s[t16][3]));
        }
#pragma unroll
        for (int off = 1; off < 4; off <<= 1) {
            mx0 = fmaxf(mx0, __shfl_xor_sync(0xffffffffu, mx0, off));
            mx1 = fmaxf(mx1, __shfl_xor_sync(0xffffffffu, mx1, off));
        }
        float mn0 = fmaxf(m0, mx0), mn1 = fmaxf(m1, mx1);
        float cr0 = __expf(m0 - mn0), cr1 = __expf(m1 - mn1);
        float rs0 = 0.f, rs1 = 0.f;
#pragma unroll
        for (int t16 = 0; t16 < 16; t16++) {
            s[t16][0] = __expf(s[t16][0] - mn0);
            s[t16][1] = __expf(s[t16][1] - mn0);
            s[t16][2] = __expf(s[t16][2] - mn1);
            s[t16][3] = __expf(s[t16][3] - mn1);
            rs0 += s[t16][0] + s[t16][1];
            rs1 += s[t16][2] + s[t16][3];
        }
#pragma unroll
        for (int off = 1; off < 4; off <<= 1) {
            rs0 += __shfl_xor_sync(0xffffffffu, rs0, off);
            rs1 += __shfl_xor_sync(0xffffffffu, rs1, off);
        }
        l0 = l0 * cr0 + rs0; m0 = mn0;
        l1 = l1 * cr1 + rs1; m1 = mn1;
#pragma unroll
        for (int nf = 0; nf < 8; nf++) {
            o[nf][0] *= cr0; o[nf][1] *= cr0;
            o[nf][2] *= cr1; o[nf][3] *= cr1;
        }

        // O += P V, ldmatrix V fragments (2 nf tiles per x4)
#pragma unroll
        for (int c = 0; c < 8; c++) {
            uint32_t ph[4], pl[4];
#pragma unroll
            for (int u = 0; u < 2; u++) {
                const float* sv = s[2 * c + u];
                ph[2 * u]     = packbf(sv[0], sv[1]);
                ph[2 * u + 1] = packbf(sv[2], sv[3]);
                __nv_bfloat162 hp0 = *(__nv_bfloat162*)&ph[2 * u];
                __nv_bfloat162 hp1 = *(__nv_bfloat162*)&ph[2 * u + 1];
                pl[2 * u]     = packbf(sv[0] - __low2float(hp0), sv[1] - __high2float(hp0));
                pl[2 * u + 1] = packbf(sv[2] - __low2float(hp1), sv[3] - __high2float(hp1));
            }
#pragma unroll
            for (int np = 0; np < 4; np++) {
                const int dl = 16 * np + rpart;
                const uint32_t off =
                    (uint32_t)(dl * 64 + (((2 * c + cadd2) ^ (dl & 7)) << 2)) * 4u;
                uint32_t vh4[4], vl4[4];
                ldmx4(vh4, sVh + off);
                ldmx4(vl4, sVl + off);
                uint32_t v0h[2] = {vh4[0], vh4[2]}, v1h[2] = {vh4[1], vh4[3]};
                uint32_t v0l[2] = {vl4[0], vl4[2]}, v1l[2] = {vl4[1], vl4[3]};
                mma16816(o[2 * np], ph, v0h);
                mma16816(o[2 * np], pl, v0h);
                mma16816(o[2 * np], ph, v0l);
                mma16816(o[2 * np + 1], ph, v1h);
                mma16816(o[2 * np + 1], pl, v1h);
                mma16816(o[2 * np + 1], ph, v1l);
            }
        }
    }

    // epilogue -> bf16 hi/lo att
    const int b = blockIdx.z, h = blockIdx.y;
    const float i0 = 1.0f / l0, i1 = 1.0f / l1;
    const int n0 = q0 + wid * 16 + lr;
#pragma unroll
    for (int nf = 0; nf < 8; nf++) {
        const int d = 8 * nf + 2 * lc2;
        const size_t cidx = (size_t)(h * DD + d) >> 1;
        {
            float v0 = o[nf][0] * i0, v1 = o[nf][1] * i0;
            __nv_bfloat16 h0 = __float2bfloat16(v0), h1 = __float2bfloat16(v1);
            size_t row = (size_t)(b * NN + n0) * CW + cidx;
            g_atth[row] = packbf(v0, v1);
            g_attl[row] = packbf(v0 - __bfloat162float(h0), v1 - __bfloat162float(h1));
        }
        {
            float v0 = o[nf][2] * i1, v1 = o[nf][3] * i1;
            __nv_bfloat16 h0 = __float2bfloat16(v0), h1 = __float2bfloat16(v1);
            size_t row = (size_t)(b * NN + n0 + 8) * CW + cidx;
            g_atth[row] = packbf(v0, v1);
            g_attl[row] = packbf(v0 - __bfloat162float(h0), v1 - __bfloat162float(h1));
        }
    }
}

// ---------------------------------------------------------------------------
__global__ __launch_bounds__(256, 2) void proj_mma(const float* __restrict__ bias,
                                                   float* __restrict__ out) {
    const int row0 = blockIdx.y * 128;
    const int col0 = blockIdx.x * 128;
    float acc[2][8][4] = {};
    bf16gemm(g_atth, g_attl, g_wph, g_wpl, row0, col0, acc);

    const int t = threadIdx.x, wid = t >> 5, lane = t & 31;
    const int wm = wid & 3, wn = wid >> 2;
    const int lr = lane >> 2, lc2 = lane & 3;
#pragma unroll
    for (int mf = 0; mf < 2; mf++) {
        const int rbase = row0 + wm * 32 + mf * 16 + lr;
#pragma unroll
        for (int half = 0; half < 2; half++) {
            const int r = rbase + half * 8;
#pragma unroll
            for (int nf = 0; nf < 8; nf++) {
                const int c = col0 + wn * 64 + nf * 8 + lc2 * 2;
                *(float2*)(out + (size_t)r * CC + c) =
                    make_float2(acc[mf][nf][half * 2] + bias[c],
                                acc[mf][nf][half * 2 + 1] + bias[c + 1]);
            }
        }
    }
}

// ---------------------------------------------------------------------------
extern "C" void kernel_launch(void* const* d_in, const int* in_sizes, int n_in,
                              void* d_out, int out_size) {
    const float* x      = (const float*)d_in[0];
    const float* w_qkv  = (const float*)d_in[1];
    const float* w_proj = (const float*)d_in[2];
    const float* b_proj = (const float*)d_in[3];
    float* out = (float*)d_out;

    cudaFuncSetAttribute(qkv_mma,  cudaFuncAttributeMaxDynamicSharedMemorySize, SMEM_GEMM);
    cudaFuncSetAttribute(proj_mma, cudaFuncAttributeMaxDynamicSharedMemorySize, SMEM_GEMM);
    cudaFuncSetAttribute(attn_mma, cudaFuncAttributeMaxDynamicSharedMemorySize, SMEM_ATTN);

    uint32_t *p_xh, *p_xl, *p_wqh, *p_wql, *p_wph, *p_wpl;
    cudaGetSymbolAddress((void**)&p_xh,  g_xh);
    cudaGetSymbolAddress((void**)&p_xl,  g_xl);
    cudaGetSymbolAddress((void**)&p_wqh, g_wqh);
    cudaGetSymbolAddress((void**)&p_wql, g_wql);
    cudaGetSymbolAddress((void**)&p_wph, g_wph);
    cudaGetSymbolAddress((void**)&p_wpl, g_wpl);

    const int n4x = MM * CC / 4, n4q = 3 * CC * CC / 4, n4p = CC * CC / 4;
    cvt_hilo<<<(n4x + 255) / 256, 256>>>(x, p_xh, p_xl, n4x);
    cvt_hilo<<<(n4q + 255) / 256, 256>>>(w_qkv, p_wqh, p_wql, n4q);
    cvt_hilo<<<(n4p + 255) / 256, 256>>>(w_proj, p_wph, p_wpl, n4p);

    dim3 g1(3 * CC / 128, MM / 128);
    qkv_mma<<<g1, 256, SMEM_GEMM>>>();

    dim3 g2(NN / 128, HH, BB);
    attn_mma<<<g2, 256, SMEM_ATTN>>>();

    dim3 g3(CC / 128, MM / 128);
    proj_mma<<<g3, 256, SMEM_GEMM>>>(b_proj, out);
}

// round 14
// speedup vs baseline: 1.0773x; 1.0773x over previous
#include <cuda_runtime.h>
#include <cuda_bf16.h>
#include <cstdint>

// MultiHeadAttention: B=2, N=2048, C=1024, H=16, D=64, fp32.
// R14: attn gets cp.async double-buffered K/V tiles (latency hiding).
//      GEMMs identical to R13 (ldmatrix + cp.async bf16 hi/lo x3).

#define BB 2
#define NN 2048
#define CC 1024
#define HH 16
#define DD 64
#define MM (BB * NN)
#define SCALE_F 0.125f
#define CW (CC / 2)

#define NCH 32
#define SST 20
#define STW (128 * SST)
#define STW4 (STW * 4)
#define SMEM_GEMM (2 * 4 * STW4)   // 81920
#define SMEM_ATTN 131072           // 2 buffers x 4 tensors x 16KB

__device__ uint32_t g_xh[(size_t)MM * CW],  g_xl[(size_t)MM * CW];
__device__ uint32_t g_wqh[(size_t)3 * CC * CW], g_wql[(size_t)3 * CC * CW];
__device__ uint32_t g_wph[(size_t)CC * CW], g_wpl[(size_t)CC * CW];
__device__ uint32_t g_qh[(size_t)BB * HH * NN * DD / 2], g_ql[(size_t)BB * HH * NN * DD / 2];
__device__ uint32_t g_kh[(size_t)BB * HH * NN * DD / 2], g_kl[(size_t)BB * HH * NN * DD / 2];
__device__ uint32_t g_vh[(size_t)BB * HH * DD * NN / 2], g_vl[(size_t)BB * HH * DD * NN / 2];
__device__ uint32_t g_atth[(size_t)MM * CW], g_attl[(size_t)MM * CW];

extern __shared__ unsigned char dynsm[];

// ---------------------------------------------------------------------------
static __device__ __forceinline__ void mma16816(float* d, const uint32_t a[4],
                                                const uint32_t b[2]) {
    asm volatile(
        "mma.sync.aligned.m16n8k16.row.col.f32.bf16.bf16.f32 "
        "{%0,%1,%2,%3}, {%4,%5,%6,%7}, {%8,%9}, {%0,%1,%2,%3};"
        : "+f"(d[0]), "+f"(d[1]), "+f"(d[2]), "+f"(d[3])
        : "r"(a[0]), "r"(a[1]), "r"(a[2]), "r"(a[3]), "r"(b[0]), "r"(b[1]));
}
static __device__ __forceinline__ void ldmx4(uint32_t* r, uint32_t saddr) {
    asm volatile("ldmatrix.sync.aligned.m8n8.x4.shared.b16 {%0,%1,%2,%3}, [%4];"
                 : "=r"(r[0]), "=r"(r[1]), "=r"(r[2]), "=r"(r[3]) : "r"(saddr));
}
static __device__ __forceinline__ uint32_t packbf(float x0, float x1) {
    __nv_bfloat162 p = __halves2bfloat162(__float2bfloat16(x0), __float2bfloat16(x1));
    return *(uint32_t*)&p;
}
static __device__ __forceinline__ void cpa16(uint32_t dst, const void* src) {
    asm volatile("cp.async.ca.shared.global [%0], [%1], 16;"
                 :: "r"(dst), "l"(src) : "memory");
}
#define CP_COMMIT() asm volatile("cp.async.commit_group;" ::: "memory")
#define CP_WAIT(n)  asm volatile("cp.async.wait_group %0;" :: "n"(n) : "memory")

// ---------------------------------------------------------------------------
__global__ __launch_bounds__(256) void cvt_hilo(const float* __restrict__ src,
                                                uint32_t* __restrict__ hi,
                                                uint32_t* __restrict__ lo, int n4) {
    int i = blockIdx.x * blockDim.x + threadIdx.x;
    if (i >= n4) return;
    float4 v = ((const float4*)src)[i];
    __nv_bfloat16 h0 = __float2bfloat16(v.x), h1 = __float2bfloat16(v.y);
    __nv_bfloat16 h2 = __float2bfloat16(v.z), h3 = __float2bfloat16(v.w);
    uint32_t hw0 = packbf(v.x, v.y), hw1 = packbf(v.z, v.w);
    uint32_t lw0 = packbf(v.x - __bfloat162float(h0), v.y - __bfloat162float(h1));
    uint32_t lw1 = packbf(v.z - __bfloat162float(h2), v.w - __bfloat162float(h3));
    ((uint2*)hi)[i] = make_uint2(hw0, hw1);
    ((uint2*)lo)[i] = make_uint2(lw0, lw1);
}

// ---------------------------------------------------------------------------
// GEMM (unchanged from R13)
// ---------------------------------------------------------------------------
static __device__ __forceinline__ void prefetch4(const uint32_t* __restrict__ Ah,
                                                 const uint32_t* __restrict__ Al,
                                                 const uint32_t* __restrict__ Bh,
                                                 const uint32_t* __restrict__ Bl,
                                                 int row0, int col0, int c,
                                                 uint32_t sbase, int t) {
#pragma unroll
    for (int i = 0; i < 2; i++) {
        int idx = t + i * 256;
        int row = idx >> 2, q = (idx & 3) * 4;
        uint32_t doff = (uint32_t)(row * SST + q) * 4u;
        size_t aoff = (size_t)(row0 + row) * CW + c * 16 + q;
        size_t boff = (size_t)(col0 + row) * CW + c * 16 + q;
        cpa16(sbase + doff,            Ah + aoff);
        cpa16(sbase + STW4 + doff,     Al + aoff);
        cpa16(sbase + 2 * STW4 + doff, Bh + boff);
        cpa16(sbase + 3 * STW4 + doff, Bl + boff);
    }
}

static __device__ __forceinline__ void bf16gemm(const uint32_t* __restrict__ Ah,
                                                const uint32_t* __restrict__ Al,
                                                const uint32_t* __restrict__ Bh,
                                                const uint32_t* __restrict__ Bl,
                                                int row0, int col0, float acc[2][8][4]) {
    const int t = threadIdx.x;
    const int wid = t >> 5, lane = t & 31;
    const int wm = wid & 3, wn = wid >> 2;
    const int lrow = lane & 7, grp = lane >> 3;
    const uint32_t sb = (uint32_t)__cvta_generic_to_shared(dynsm);

    const int rpart = lrow + ((grp & 1) << 3);
    const int cadd = (grp >> 1) << 2;

    prefetch4(Ah, Al, Bh, Bl, row0, col0, 0, sb, t);
    CP_COMMIT();

    for (int c = 0; c < NCH; c++) {
        const int buf = c & 1;
        if (c + 1 < NCH) {
            prefetch4(Ah, Al, Bh, Bl, row0, col0, c + 1,
                      sb + (uint32_t)((c + 1) & 1) * 4 * STW4, t);
            CP_COMMIT();
            CP_WAIT(1);
        } else {
            CP_WAIT(0);
        }
        __syncthreads();

        const uint32_t base = sb + (uint32_t)buf * 4 * STW4;
#pragma unroll
        for (int k16 = 0; k16 < 2; k16++) {
            const int colu = k16 * 8 + cadd;
            uint32_t afh[2][4], afl[2][4];
#pragma unroll
            for (int mf = 0; mf < 2; mf++) {
                const int r = wm * 32 + mf * 16 + rpart;
                const uint32_t off = (uint32_t)(r * SST + colu) * 4u;
                ldmx4(afh[mf], base + off);
                ldmx4(afl[mf], base + STW4 + off);
            }
#pragma unroll
            for (int nfp = 0; nfp < 4; nfp++) {
                const int n = wn * 64 + nfp * 16 + rpart;
                const uint32_t off = (uint32_t)(n * SST + colu) * 4u;
                uint32_t bfh[4], bfl[4];
                ldmx4(bfh, base + 2 * STW4 + off);
                ldmx4(bfl, base + 3 * STW4 + off);
                uint32_t b0h[2] = {bfh[0], bfh[2]}, b1h[2] = {bfh[1], bfh[3]};
                uint32_t b0l[2] = {bfl[0], bfl[2]}, b1l[2] = {bfl[1], bfl[3]};
#pragma unroll
                for (int mf = 0; mf < 2; mf++) {
                    mma16816(acc[mf][2 * nfp],     afh[mf], b0h);
                    mma16816(acc[mf][2 * nfp],     afl[mf], b0h);
                    mma16816(acc[mf][2 * nfp],     afh[mf], b0l);
                    mma16816(acc[mf][2 * nfp + 1], afh[mf], b1h);
                    mma16816(acc[mf][2 * nfp + 1], afl[mf], b1h);
                    mma16816(acc[mf][2 * nfp + 1], afh[mf], b1l);
                }
            }
        }
        __syncthreads();
    }
}

// ---------------------------------------------------------------------------
// qkv (unchanged from R13)
// ---------------------------------------------------------------------------
__global__ __launch_bounds__(256, 2) void qkv_mma() {
    const int row0 = blockIdx.y * 128;
    const int col0 = blockIdx.x * 128;
    float acc[2][8][4] = {};
    bf16gemm(g_xh, g_xl, g_wqh, g_wql, row0, col0, acc);

    const int t = threadIdx.x, wid = t >> 5, lane = t & 31;
    const int wm = wid & 3, wn = wid >> 2;
    const int lr = lane >> 2, lc2 = lane & 3;
    const int which = col0 >> 10;
    const int colrem0 = (col0 & (CC - 1)) + wn * 64;
#pragma unroll
    for (int mf = 0; mf < 2; mf++) {
        const int rbase = row0 + wm * 32 + mf * 16 + lr;
#pragma unroll
        for (int half = 0; half < 2; half++) {
            const int r = rbase + half * 8;
            const int b = r >> 11, n = r & (NN - 1);
#pragma unroll
            for (int nf = 0; nf < 8; nf++) {
                const int c = colrem0 + nf * 8 + lc2 * 2;
                float v0 = acc[mf][nf][half * 2];
                float v1 = acc[mf][nf][half * 2 + 1];
                const int h = c >> 6, d = c & 63;
                if (which == 0) { v0 *= SCALE_F; v1 *= SCALE_F; }
                __nv_bfloat16 h0 = __float2bfloat16(v0);
                __nv_bfloat16 h1 = __float2bfloat16(v1);
                __nv_bfloat16 e0 = __float2bfloat16(v0 - __bfloat162float(h0));
                __nv_bfloat16 e1 = __float2bfloat16(v1 - __bfloat162float(h1));
                if (which == 2) {
                    size_t base = ((size_t)(b * HH + h) * DD + d) * NN + n;
                    __nv_bfloat16* vh = (__nv_bfloat16*)g_vh;
                    __nv_bfloat16* vl = (__nv_bfloat16*)g_vl;
                    vh[base] = h0; vh[base + NN] = h1;
                    vl[base] = e0; vl[base + NN] = e1;
                } else {
                    __nv_bfloat162 hp = __halves2bfloat162(h0, h1);
                    __nv_bfloat162 lp = __halves2bfloat162(e0, e1);
                    uint32_t* ah = which ? g_kh : g_qh;
                    uint32_t* al = which ? g_kl : g_ql;
                    size_t idx = ((size_t)(b * HH + h) * NN + n) * 32 + (d >> 1);
                    ah[idx] = *(uint32_t*)&hp;
                    al[idx] = *(uint32_t*)&lp;
                }
            }
        }
    }
}

// ---------------------------------------------------------------------------
// Attention: R13 compute core + cp.async double-buffered K/V tiles.
// Buffer b at byte offset b*65536: Kh +0, Kl +16384, Vh +32768, Vl +49152.
// ---------------------------------------------------------------------------
static __device__ __forceinline__ void attn_issue_tile(
    const uint4* __restrict__ gkh, const uint4* __restrict__ gkl,
    const uint4* __restrict__ gvh, const uint4* __restrict__ gvl,
    int k0, uint32_t sB, int t) {
#pragma unroll
    for (int i = 0; i < 4; i++) {
        int idx = t + i * 256;
        int key = idx >> 3, c4 = idx & 7;
        uint32_t dst = (uint32_t)(key * 8 + (c4 ^ (key & 7))) * 16u;
        cpa16(sB + dst,         &gkh[(size_t)(k0 + key) * 8 + c4]);
        cpa16(sB + 16384 + dst, &gkl[(size_t)(k0 + key) * 8 + c4]);
        int d = idx >> 4, v4 = idx & 15;
        uint32_t vdst = (uint32_t)(d * 16 + (v4 ^ (d & 7))) * 16u;
        cpa16(sB + 32768 + vdst, &gvh[(size_t)d * 256 + (k0 >> 3) + v4]);
        cpa16(sB + 49152 + vdst, &gvl[(size_t)d * 256 + (k0 >> 3) + v4]);
    }
}

__global__ __launch_bounds__(256) void attn_mma() {
    const int t = threadIdx.x, wid = t >> 5, lane = t & 31;
    const int lr = lane >> 2, lc2 = lane & 3;
    const int lrow = lane & 7, grp = lane >> 3;
    const int rpart = lrow + ((grp & 1) << 3);
    const int cadd2 = (grp >> 1);
    const int bh = blockIdx.z * HH + blockIdx.y;
    const int q0 = blockIdx.x * 128;
    const uint32_t sb = (uint32_t)__cvta_generic_to_shared(dynsm);

    const uint4* gkh = (const uint4*)g_kh + ((size_t)bh * NN) * 8;
    const uint4* gkl = (const uint4*)g_kl + ((size_t)bh * NN) * 8;
    const uint4* gvh = (const uint4*)g_vh + ((size_t)bh * DD) * 256;
    const uint4* gvl = (const uint4*)g_vl + ((size_t)bh * DD) * 256;

    // stage tile 0 while we fetch Q fragments
    attn_issue_tile(gkh, gkl, gvh, gvl, 0, sb, t);
    CP_COMMIT();

    uint32_t qh[4][4], ql[4][4];
    {
        const size_t rbase = ((size_t)bh * NN + q0 + wid * 16) * 32;
        const uint32_t* r0h = g_qh + rbase + (size_t)lr * 32;
        const uint32_t* r1h = r0h + 8 * 32;
        const uint32_t* r0l = g_ql + rbase + (size_t)lr * 32;
        const uint32_t* r1l = r0l + 8 * 32;
#pragma unroll
        for (int c = 0; c < 4; c++) {
            qh[c][0] = r0h[8 * c + lc2];     qh[c][1] = r1h[8 * c + lc2];
            qh[c][2] = r0h[8 * c + lc2 + 4]; qh[c][3] = r1h[8 * c + lc2 + 4];
            ql[c][0] = r0l[8 * c + lc2];     ql[c][1] = r1l[8 * c + lc2];
            ql[c][2] = r0l[8 * c + lc2 + 4]; ql[c][3] = r1l[8 * c + lc2 + 4];
        }
    }

    float o[8][4] = {};
    float m0 = -1e30f, m1 = -1e30f, l0 = 0.f, l1 = 0.f;

    for (int it = 0; it < NN / 128; it++) {
        const int buf = it & 1;
        if (it + 1 < NN / 128) {
            attn_issue_tile(gkh, gkl, gvh, gvl, (it + 1) * 128,
                            sb + (uint32_t)(buf ^ 1) * 65536, t);
            CP_COMMIT();
            CP_WAIT(1);
        } else {
            CP_WAIT(0);
        }
        __syncthreads();

        const uint32_t sKh = sb + (uint32_t)buf * 65536;
        const uint32_t sKl = sKh + 16384;
        const uint32_t sVh = sKh + 32768;
        const uint32_t sVl = sKh + 49152;

        // S = Q K^T
        float s[16][4] = {};
#pragma unroll
        for (int c = 0; c < 4; c++) {
#pragma unroll
            for (int tp = 0; tp < 8; tp++) {
                const int key = 16 * tp + rpart;
                const uint32_t off =
                    (uint32_t)(key * 32 + (((2 * c + cadd2) ^ (key & 7)) << 2)) * 4u;
                uint32_t kh4[4], kl4[4];
                ldmx4(kh4, sKh + off);
                ldmx4(kl4, sKl + off);
                uint32_t b0h[2] = {kh4[0], kh4[2]}, b1h[2] = {kh4[1], kh4[3]};
                uint32_t b0l[2] = {kl4[0], kl4[2]}, b1l[2] = {kl4[1], kl4[3]};
                mma16816(s[2 * tp], qh[c], b0h);
                mma16816(s[2 * tp], ql[c], b0h);
                mma16816(s[2 * tp], qh[c], b0l);
                mma16816(s[2 * tp + 1], qh[c], b1h);
                mma16816(s[2 * tp + 1], ql[c], b1h);
                mma16816(s[2 * tp + 1], qh[c], b1l);
            }
        }

        // online softmax
        float mx0 = -1e30f, mx1 = -1e30f;
#pragma unroll
        for (int t16 = 0; t16 < 16; t16++) {
            mx0 = fmaxf(mx0, fmaxf(s[t16][0], s[t16][1]));
            mx1 = fmaxf(mx1, fmaxf(s[t16][2], s[t16][3]));
        }
#pragma unroll
        for (int off = 1; off < 4; off <<= 1) {
            mx0 = fmaxf(mx0, __shfl_xor_sync(0xffffffffu, mx0, off));
            mx1 = fmaxf(mx1, __shfl_xor_sync(0xffffffffu, mx1, off));
        }
        float mn0 = fmaxf(m0, mx0), mn1 = fmaxf(m1, mx1);
        float cr0 = __expf(m0 - mn0), cr1 = __expf(m1 - mn1);
        float rs0 = 0.f, rs1 = 0.f;
#pragma unroll
        for (int t16 = 0; t16 < 16; t16++) {
            s[t16][0] = __expf(s[t16][0] - mn0);
            s[t16][1] = __expf(s[t16][1] - mn0);
            s[t16][2] = __expf(s[t16][2] - mn1);
            s[t16][3] = __expf(s[t16][3] - mn1);
            rs0 += s[t16][0] + s[t16][1];
            rs1 += s[t16][2] + s[t16][3];
        }
#pragma unroll
        for (int off = 1; off < 4; off <<= 1) {
            rs0 += __shfl_xor_sync(0xffffffffu, rs0, off);
            rs1 += __shfl_xor_sync(0xffffffffu, rs1, off);
        }
        l0 = l0 * cr0 + rs0; m0 = mn0;
        l1 = l1 * cr1 + rs1; m1 = mn1;
#pragma unroll
        for (int nf = 0; nf < 8; nf++) {
            o[nf][0] *= cr0; o[nf][1] *= cr0;
            o[nf][2] *= cr1; o[nf][3] *= cr1;
        }

        // O += P V
#pragma unroll
        for (int c = 0; c < 8; c++) {
            uint32_t ph[4], pl[4];
#pragma unroll
            for (int u = 0; u < 2; u++) {
                const float* sv = s[2 * c + u];
                ph[2 * u]     = packbf(sv[0], sv[1]);
                ph[2 * u + 1] = packbf(sv[2], sv[3]);
                __nv_bfloat162 hp0 = *(__nv_bfloat162*)&ph[2 * u];
                __nv_bfloat162 hp1 = *(__nv_bfloat162*)&ph[2 * u + 1];
                pl[2 * u]     = packbf(sv[0] - __low2float(hp0), sv[1] - __high2float(hp0));
                pl[2 * u + 1] = packbf(sv[2] - __low2float(hp1), sv[3] - __high2float(hp1));
            }
#pragma unroll
            for (int np = 0; np < 4; np++) {
                const int dl = 16 * np + rpart;
                const uint32_t off =
                    (uint32_t)(dl * 64 + (((2 * c + cadd2) ^ (dl & 7)) << 2)) * 4u;
                uint32_t vh4[4], vl4[4];
                ldmx4(vh4, sVh + off);
                ldmx4(vl4, sVl + off);
                uint32_t v0h[2] = {vh4[0], vh4[2]}, v1h[2] = {vh4[1], vh4[3]};
                uint32_t v0l[2] = {vl4[0], vl4[2]}, v1l[2] = {vl4[1], vl4[3]};
                mma16816(o[2 * np], ph, v0h);
                mma16816(o[2 * np], pl, v0h);
                mma16816(o[2 * np], ph, v0l);
                mma16816(o[2 * np + 1], ph, v1h);
                mma16816(o[2 * np + 1], pl, v1h);
                mma16816(o[2 * np + 1], ph, v1l);
            }
        }
        __syncthreads();   // reads done before next iter overwrites this buffer
    }

    // epilogue -> bf16 hi/lo att
    const int b = blockIdx.z, h = blockIdx.y;
    const float i0 = 1.0f / l0, i1 = 1.0f / l1;
    const int n0 = q0 + wid * 16 + lr;
#pragma unroll
    for (int nf = 0; nf < 8; nf++) {
        const int d = 8 * nf + 2 * lc2;
        const size_t cidx = (size_t)(h * DD + d) >> 1;
        {
            float v0 = o[nf][0] * i0, v1 = o[nf][1] * i0;
            __nv_bfloat16 h0 = __float2bfloat16(v0), h1 = __float2bfloat16(v1);
            size_t row = (size_t)(b * NN + n0) * CW + cidx;
            g_atth[row] = packbf(v0, v1);
            g_attl[row] = packbf(v0 - __bfloat162float(h0), v1 - __bfloat162float(h1));
        }
        {
            float v0 = o[nf][2] * i1, v1 = o[nf][3] * i1;
            __nv_bfloat16 h0 = __float2bfloat16(v0), h1 = __float2bfloat16(v1);
            size_t row = (size_t)(b * NN + n0 + 8) * CW + cidx;
            g_atth[row] = packbf(v0, v1);
            g_attl[row] = packbf(v0 - __bfloat162float(h0), v1 - __bfloat162float(h1));
        }
    }
}

// ---------------------------------------------------------------------------
__global__ __launch_bounds__(256, 2) void proj_mma(const float* __restrict__ bias,
                                                   float* __restrict__ out) {
    const int row0 = blockIdx.y * 128;
    const int col0 = blockIdx.x * 128;
    float acc[2][8][4] = {};
    bf16gemm(g_atth, g_attl, g_wph, g_wpl, row0, col0, acc);

    const int t = threadIdx.x, wid = t >> 5, lane = t & 31;
    const int wm = wid & 3, wn = wid >> 2;
    const int lr = lane >> 2, lc2 = lane & 3;
#pragma unroll
    for (int mf = 0; mf < 2; mf++) {
        const int rbase = row0 + wm * 32 + mf * 16 + lr;
#pragma unroll
        for (int half = 0; half < 2; half++) {
            const int r = rbase + half * 8;
#pragma unroll
            for (int nf = 0; nf < 8; nf++) {
                const int c = col0 + wn * 64 + nf * 8 + lc2 * 2;
                *(float2*)(out + (size_t)r * CC + c) =
                    make_float2(acc[mf][nf][half * 2] + bias[c],
                                acc[mf][nf][half * 2 + 1] + bias[c + 1]);
            }
        }
    }
}

// ---------------------------------------------------------------------------
extern "C" void kernel_launch(void* const* d_in, const int* in_sizes, int n_in,
                              void* d_out, int out_size) {
    const float* x      = (const float*)d_in[0];
    const float* w_qkv  = (const float*)d_in[1];
    const float* w_proj = (const float*)d_in[2];
    const float* b_proj = (const float*)d_in[3];
    float* out = (float*)d_out;

    cudaFuncSetAttribute(qkv_mma,  cudaFuncAttributeMaxDynamicSharedMemorySize, SMEM_GEMM);
    cudaFuncSetAttribute(proj_mma, cudaFuncAttributeMaxDynamicSharedMemorySize, SMEM_GEMM);
    cudaFuncSetAttribute(attn_mma, cudaFuncAttributeMaxDynamicSharedMemorySize, SMEM_ATTN);

    uint32_t *p_xh, *p_xl, *p_wqh, *p_wql, *p_wph, *p_wpl;
    cudaGetSymbolAddress((void**)&p_xh,  g_xh);
    cudaGetSymbolAddress((void**)&p_xl,  g_xl);
    cudaGetSymbolAddress((void**)&p_wqh, g_wqh);
    cudaGetSymbolAddress((void**)&p_wql, g_wql);
    cudaGetSymbolAddress((void**)&p_wph, g_wph);
    cudaGetSymbolAddress((void**)&p_wpl, g_wpl);

    const int n4x = MM * CC / 4, n4q = 3 * CC * CC / 4, n4p = CC * CC / 4;
    cvt_hilo<<<(n4x + 255) / 256, 256>>>(x, p_xh, p_xl, n4x);
    cvt_hilo<<<(n4q + 255) / 256, 256>>>(w_qkv, p_wqh, p_wql, n4q);
    cvt_hilo<<<(n4p + 255) / 256, 256>>>(w_proj, p_wph, p_wpl, n4p);

    dim3 g1(3 * CC / 128, MM / 128);
    qkv_mma<<<g1, 256, SMEM_GEMM>>>();

    dim3 g2(NN / 128, HH, BB);
    attn_mma<<<g2, 256, SMEM_ATTN>>>();

    dim3 g3(CC / 128, MM / 128);
    proj_mma<<<g3, 256, SMEM_GEMM>>>(b_proj, out);
}